// round 1
// baseline (speedup 1.0000x reference)
#include <cuda_runtime.h>
#include <cuda_fp16.h>
#include <cstdint>

#define LSEQ 2048
#define NH   8
#define DDIM 64
#define NB   4
#define NBH  32          // NB*NH
#define MDIST 128
#define DBINS 257
#define LDP  72          // padded shared row stride (halves): 144B = 9*16B -> conflict-free ldmatrix

// ---------------- scratch (device globals; no runtime alloc) ----------------
__device__ __half g_qkin[8192 * 256];       // x+pe, fp16
__device__ __half g_Wt[1024 * 256];         // [Wq|Wk]^T, n-major rows, k contiguous
__device__ __half g_Q[NBH * LSEQ * DDIM];   // scaled by d^-0.5, +bias
__device__ __half g_K[NBH * LSEQ * DDIM];
__device__ float  g_V[NBH * LSEQ];          // Vflip[b,h,k] = sigmoid(x[b,L-1-k] . Wv[:,h])
__device__ float  g_S[NBH * DBINS];         // diagonal-bin accumulator

// ---------------- mma helpers ----------------
__device__ __forceinline__ uint32_t sptr(const void* p) {
    return (uint32_t)__cvta_generic_to_shared(p);
}

__device__ __forceinline__ void ldsm4(uint32_t& r0, uint32_t& r1, uint32_t& r2, uint32_t& r3,
                                      uint32_t addr) {
    asm volatile("ldmatrix.sync.aligned.m8n8.x4.shared.b16 {%0,%1,%2,%3}, [%4];\n"
                 : "=r"(r0), "=r"(r1), "=r"(r2), "=r"(r3) : "r"(addr));
}

__device__ __forceinline__ void mma16816(float* c, uint32_t a0, uint32_t a1, uint32_t a2,
                                         uint32_t a3, uint32_t b0, uint32_t b1) {
    asm volatile(
        "mma.sync.aligned.m16n8k16.row.col.f32.f16.f16.f32 "
        "{%0,%1,%2,%3},{%4,%5,%6,%7},{%8,%9},{%0,%1,%2,%3};\n"
        : "+f"(c[0]), "+f"(c[1]), "+f"(c[2]), "+f"(c[3])
        : "r"(a0), "r"(a1), "r"(a2), "r"(a3), "r"(b0), "r"(b1));
}

// 64x64 (MxN) += Qs[64x64] * Ks[64x64]^T, inner dim 64.
// Qs rows = M (k contiguous), Ks rows = N (k contiguous). Warp (wy 0..3, wx 0..1)
// owns a 16x32 tile. acc[nt*4+..]: nt -> n offset nt*8 within the warp's 32 cols.
__device__ __forceinline__ void mma_tile_64(const __half* Qs, const __half* Ks,
                                            float acc[16], int lane, int wy, int wx) {
    uint32_t a_addr = sptr(Qs + (wy * 16 + (lane & 15)) * LDP + ((lane >> 4) << 3));
    int brow = wx * 32 + (lane & 7) + ((lane >> 4) << 3);
    int bcol = ((lane >> 3) & 1) << 3;
    uint32_t b_addr0 = sptr(Ks + brow * LDP + bcol);
    uint32_t b_addr1 = b_addr0 + 16 * LDP * 2;  // +16 n-rows
#pragma unroll
    for (int kc = 0; kc < 4; kc++) {
        uint32_t a0, a1, a2, a3, b0, b1, b2, b3, b4, b5, b6, b7;
        ldsm4(a0, a1, a2, a3, a_addr + kc * 32);
        ldsm4(b0, b1, b2, b3, b_addr0 + kc * 32);
        ldsm4(b4, b5, b6, b7, b_addr1 + kc * 32);
        mma16816(acc + 0,  a0, a1, a2, a3, b0, b1);
        mma16816(acc + 4,  a0, a1, a2, a3, b2, b3);
        mma16816(acc + 8,  a0, a1, a2, a3, b4, b5);
        mma16816(acc + 12, a0, a1, a2, a3, b6, b7);
    }
}

// copy 64x64 halves (global, row stride STRIDE halves) into padded shared tile
#define LOAD_TILE(DST, SRC, STRIDE)                                                   \
    {                                                                                 \
        int r_ = tid >> 3, c_ = (tid & 7) << 3;                                       \
        *(int4*)((DST) + r_ * LDP + c_) = *(const int4*)((SRC) + r_ * (STRIDE) + c_); \
        *(int4*)((DST) + (r_ + 32) * LDP + c_) =                                      \
            *(const int4*)((SRC) + (r_ + 32) * (STRIDE) + c_);                        \
    }

// ---------------- kernel 1: prep ----------------
__global__ void prep_kernel(const float* __restrict__ x, const float* __restrict__ pe,
                            const float* __restrict__ Wq, const float* __restrict__ Wk) {
    int idx = blockIdx.x * 256 + threadIdx.x;
    if (idx < 8192 * 256) {
        int row = idx >> 8;
        int l = row & (LSEQ - 1);
        int c = idx & 255;
        g_qkin[idx] = __float2half(x[idx] + pe[l * 256 + c]);
        return;
    }
    int i2 = idx - 8192 * 256;
    if (i2 < 1024 * 256) {
        int n = i2 >> 8, kk = i2 & 255;
        float w = (n < 512) ? Wq[kk * 512 + n] : Wk[kk * 512 + (n - 512)];
        g_Wt[i2] = __float2half(w);
        return;
    }
    int i3 = i2 - 1024 * 256;
    if (i3 < NBH * DBINS) g_S[i3] = 0.f;
}

// ---------------- kernel 2: Q/K projection GEMM ----------------
__global__ void __launch_bounds__(256) proj_kernel(const float* __restrict__ bq,
                                                   const float* __restrict__ bk) {
    __shared__ __half As[64 * LDP];
    __shared__ __half Bs[64 * LDP];
    int tid = threadIdx.x, lane = tid & 31, w = tid >> 5, wy = w >> 1, wx = w & 1;
    int m0 = blockIdx.x << 6, n0 = blockIdx.y << 6;
    float acc[16];
#pragma unroll
    for (int i = 0; i < 16; i++) acc[i] = 0.f;
    for (int ks = 0; ks < 4; ks++) {
        __syncthreads();
        LOAD_TILE(As, g_qkin + m0 * 256 + (ks << 6), 256);
        LOAD_TILE(Bs, g_Wt + n0 * 256 + (ks << 6), 256);
        __syncthreads();
        mma_tile_64(As, Bs, acc, lane, wy, wx);
    }
    int g = lane >> 2, tc = lane & 3;
#pragma unroll
    for (int nt = 0; nt < 4; nt++) {
#pragma unroll
        for (int hh = 0; hh < 2; hh++) {
            int row = m0 + wy * 16 + g + (hh << 3);
            int col = n0 + wx * 32 + nt * 8 + tc * 2;
            float v0 = acc[nt * 4 + hh * 2 + 0];
            float v1 = acc[nt * 4 + hh * 2 + 1];
            int b = row >> 11, l = row & (LSEQ - 1);
            if (col < 512) {
                v0 = (v0 + bq[col]) * 0.125f;     // fold d^-0.5 into Q
                v1 = (v1 + bq[col + 1]) * 0.125f;
                int hd = col >> 6, dd = col & 63;
                *(__half2*)(g_Q + ((b * NH + hd) * LSEQ + l) * DDIM + dd) =
                    __floats2half2_rn(v0, v1);
            } else {
                int cj = col - 512;
                v0 += bk[cj];
                v1 += bk[cj + 1];
                int hd = cj >> 6, dd = cj & 63;
                *(__half2*)(g_K + ((b * NH + hd) * LSEQ + l) * DDIM + dd) =
                    __floats2half2_rn(v0, v1);
            }
        }
    }
}

// ---------------- kernel 3: V (sigmoid(x @ Wv), flipped) ----------------
__global__ void __launch_bounds__(256) v_kernel(const float* __restrict__ x,
                                                const float* __restrict__ Wv) {
    __shared__ float Wsh[256 * 8];
    __shared__ float Xsh[32 * 257];
    int tid = threadIdx.x;
    for (int i = tid; i < 2048; i += 256) Wsh[i] = Wv[i];
    int row0 = blockIdx.x * 32;  // global (b*L + l)
    for (int i = tid; i < 8192; i += 256) {
        int r = i >> 8, c = i & 255;
        Xsh[r * 257 + c] = x[(row0 + r) * 256 + c];
    }
    __syncthreads();
    int r = tid >> 3, h = tid & 7;
    int bl = row0 + r;
    float s = 0.f;
#pragma unroll 8
    for (int kk = 0; kk < 256; kk++) s += Xsh[r * 257 + kk] * Wsh[kk * 8 + h];
    float v = 1.f / (1.f + __expf(-s));
    int b = bl >> 11, l = bl & (LSEQ - 1);
    g_V[(b * NH + h) * LSEQ + (LSEQ - 1 - l)] = v;
}

// ---------------- kernel 4: attention (denominators + banded numerators) ----------------
__global__ void __launch_bounds__(256) attn_kernel() {
    __shared__ __half Qs[64 * LDP];
    __shared__ __half Ks[64 * LDP];
    __shared__ float dsh[64];
    __shared__ float Ssh[DBINS];
    int tid = threadIdx.x, lane = tid & 31, w = tid >> 5, wy = w >> 1, wx = w & 1;
    int qt = blockIdx.x, bh = blockIdx.y;
    int q0 = qt << 6;
    const __half* Qg = g_Q + (bh * LSEQ + q0) * DDIM;
    const __half* Kg = g_K + bh * LSEQ * DDIM;

    LOAD_TILE(Qs, Qg, DDIM);
    if (tid < 64) dsh[tid] = 0.f;
    if (tid < DBINS) Ssh[tid] = 0.f;
    if (tid == 255) Ssh[256] = 0.f;

    int g = lane >> 2, tc = lane & 3;
    float dsum0 = 0.f, dsum1 = 0.f;

    // Phase 1: softmax denominators over all keys (no max shift needed: |s| <~ 5)
    for (int kt = 0; kt < 32; kt++) {
        __syncthreads();
        LOAD_TILE(Ks, Kg + (kt << 6) * DDIM, DDIM);
        __syncthreads();
        float acc[16];
#pragma unroll
        for (int i = 0; i < 16; i++) acc[i] = 0.f;
        mma_tile_64(Qs, Ks, acc, lane, wy, wx);
#pragma unroll
        for (int nt = 0; nt < 4; nt++) {
            dsum0 += __expf(acc[nt * 4 + 0]) + __expf(acc[nt * 4 + 1]);
            dsum1 += __expf(acc[nt * 4 + 2]) + __expf(acc[nt * 4 + 3]);
        }
    }
    atomicAdd(&dsh[wy * 16 + g], dsum0);
    atomicAdd(&dsh[wy * 16 + g + 8], dsum1);
    __syncthreads();
    if (tid < 64) dsh[tid] = 1.f / dsh[tid];

    // Phase 2: band tiles only, bin by diagonal j = 128 + k - q
    const float* Vg = g_V + bh * LSEQ;
    int kt_lo = qt >= 2 ? qt - 2 : 0;
    int kt_hi = qt <= 29 ? qt + 2 : 31;
    for (int kt = kt_lo; kt <= kt_hi; kt++) {
        __syncthreads();
        LOAD_TILE(Ks, Kg + (kt << 6) * DDIM, DDIM);
        __syncthreads();
        float acc[16];
#pragma unroll
        for (int i = 0; i < 16; i++) acc[i] = 0.f;
        mma_tile_64(Qs, Ks, acc, lane, wy, wx);
#pragma unroll
        for (int nt = 0; nt < 4; nt++) {
            int kb = (kt << 6) + wx * 32 + nt * 8 + tc * 2;
#pragma unroll
            for (int hh = 0; hh < 2; hh++) {
                int q = q0 + wy * 16 + g + (hh << 3);
                float inv = dsh[wy * 16 + g + (hh << 3)];
#pragma unroll
                for (int cc = 0; cc < 2; cc++) {
                    int k = kb + cc;
                    int j = MDIST + k - q;
                    if (j >= 0 && j < DBINS) {
                        float e = __expf(acc[nt * 4 + hh * 2 + cc]);
                        atomicAdd(&Ssh[j], e * inv * Vg[k]);
                    }
                }
            }
        }
    }
    __syncthreads();
    if (tid < DBINS) atomicAdd(&g_S[bh * DBINS + tid], Ssh[tid]);
    if (tid == 255) atomicAdd(&g_S[bh * DBINS + 256], Ssh[256]);
}

// ---------------- kernel 5: window smoothing + output ----------------
__global__ void final_kernel(float* __restrict__ out) {
    int idx = blockIdx.x * 256 + threadIdx.x;
    if (idx >= NB * DBINS * NH) return;
    int h = idx & 7;
    int j = (idx >> 3) % DBINS;
    int b = idx / (DBINS * NH);
    const float* S = g_S + (b * NH + h) * DBINS;
    float s = S[j];
    float cnt = 1.f;
    if (j > 0)        { s += S[j - 1]; cnt += 1.f; }
    if (j < DBINS - 1){ s += S[j + 1]; cnt += 1.f; }
    out[idx] = s / cnt;  // out layout: (B, D, H) row-major = (b*257 + j)*8 + h
}

// ---------------- launch ----------------
extern "C" void kernel_launch(void* const* d_in, const int* in_sizes, int n_in,
                              void* d_out, int out_size) {
    const float* x  = (const float*)d_in[0];
    const float* pe = (const float*)d_in[1];
    const float* Wq = (const float*)d_in[2];
    const float* bq = (const float*)d_in[3];
    const float* Wk = (const float*)d_in[4];
    const float* bk = (const float*)d_in[5];
    const float* Wv = (const float*)d_in[6];
    float* out = (float*)d_out;

    int prep_total = 8192 * 256 + 1024 * 256 + NBH * DBINS;
    prep_kernel<<<(prep_total + 255) / 256, 256>>>(x, pe, Wq, Wk);
    proj_kernel<<<dim3(128, 16), 256>>>(bq, bk);
    v_kernel<<<256, 256>>>(x, Wv);
    attn_kernel<<<dim3(32, 32), 256>>>();
    final_kernel<<<(NB * DBINS * NH + 255) / 256, 256>>>(out);
}

// round 2
// speedup vs baseline: 1.1388x; 1.1388x over previous
#include <cuda_runtime.h>
#include <cuda_fp16.h>
#include <cstdint>

#define LSEQ 2048
#define NH   8
#define DDIM 64
#define NB   4
#define NBH  32          // NB*NH
#define MDIST 128
#define DBINS 257
#define LDP  72          // padded shared row stride (halves): 144B -> conflict-free ldmatrix
#define LOG2E 1.4426950408889634f

// ---------------- scratch (device globals; no runtime alloc) ----------------
__device__ __half g_qkin[8192 * 256];       // x+pe, fp16
__device__ __half g_Wt[1024 * 256];         // [Wq|Wk]^T, n-major rows, k contiguous
__device__ __half g_Q[NBH * LSEQ * DDIM];   // scaled by d^-0.5 * log2(e), +bias
__device__ __half g_K[NBH * LSEQ * DDIM];
__device__ float  g_V[NBH * LSEQ];          // Vflip[b,h,k] = sigmoid(x[b,L-1-k] . Wv[:,h])
__device__ float  g_S[NBH * DBINS];         // diagonal-bin accumulator

// ---------------- helpers ----------------
__device__ __forceinline__ uint32_t sptr(const void* p) {
    return (uint32_t)__cvta_generic_to_shared(p);
}

__device__ __forceinline__ float ex2f(float x) {
    float r;
    asm("ex2.approx.f32 %0, %1;\n" : "=f"(r) : "f"(x));
    return r;
}

__device__ __forceinline__ void ldsm4(uint32_t& r0, uint32_t& r1, uint32_t& r2, uint32_t& r3,
                                      uint32_t addr) {
    asm volatile("ldmatrix.sync.aligned.m8n8.x4.shared.b16 {%0,%1,%2,%3}, [%4];\n"
                 : "=r"(r0), "=r"(r1), "=r"(r2), "=r"(r3) : "r"(addr));
}

__device__ __forceinline__ void mma16816(float* c, uint32_t a0, uint32_t a1, uint32_t a2,
                                         uint32_t a3, uint32_t b0, uint32_t b1) {
    asm volatile(
        "mma.sync.aligned.m16n8k16.row.col.f32.f16.f16.f32 "
        "{%0,%1,%2,%3},{%4,%5,%6,%7},{%8,%9},{%0,%1,%2,%3};\n"
        : "+f"(c[0]), "+f"(c[1]), "+f"(c[2]), "+f"(c[3])
        : "r"(a0), "r"(a1), "r"(a2), "r"(a3), "r"(b0), "r"(b1));
}

__device__ __forceinline__ void cp_async16(uint32_t dst, const void* src) {
    asm volatile("cp.async.ca.shared.global [%0], [%1], 16;\n" :: "r"(dst), "l"(src));
}
__device__ __forceinline__ void cp_commit() { asm volatile("cp.async.commit_group;\n"); }
__device__ __forceinline__ void cp_wait1()  { asm volatile("cp.async.wait_group 1;\n"); }

// async copy of a 64x64 half tile (global row stride = 64) into padded shared tile
__device__ __forceinline__ void cp_tile(__half* dst, const __half* src, int tid) {
    int r = tid >> 3, c = (tid & 7) << 3;
    cp_async16(sptr(dst + r * LDP + c), src + r * 64 + c);
    cp_async16(sptr(dst + (r + 32) * LDP + c), src + (r + 32) * 64 + c);
}

// B-side of 64x64 MMA with preloaded A fragments.
__device__ __forceinline__ void mma_b(const __half* Ks, const uint32_t A[4][4], float acc[16],
                                      int lane, int wx) {
    int brow = wx * 32 + (lane & 7) + ((lane >> 4) << 3);
    int bcol = ((lane >> 3) & 1) << 3;
    uint32_t b_addr0 = sptr(Ks + brow * LDP + bcol);
    uint32_t b_addr1 = b_addr0 + 16 * LDP * 2;
#pragma unroll
    for (int kc = 0; kc < 4; kc++) {
        uint32_t b0, b1, b2, b3, b4, b5, b6, b7;
        ldsm4(b0, b1, b2, b3, b_addr0 + kc * 32);
        ldsm4(b4, b5, b6, b7, b_addr1 + kc * 32);
        mma16816(acc + 0,  A[kc][0], A[kc][1], A[kc][2], A[kc][3], b0, b1);
        mma16816(acc + 4,  A[kc][0], A[kc][1], A[kc][2], A[kc][3], b2, b3);
        mma16816(acc + 8,  A[kc][0], A[kc][1], A[kc][2], A[kc][3], b4, b5);
        mma16816(acc + 12, A[kc][0], A[kc][1], A[kc][2], A[kc][3], b6, b7);
    }
}

// sync-copy 64x64 halves (global stride STRIDE) into padded shared tile (for proj kernel)
#define LOAD_TILE(DST, SRC, STRIDE)                                                   \
    {                                                                                 \
        int r_ = tid >> 3, c_ = (tid & 7) << 3;                                       \
        *(int4*)((DST) + r_ * LDP + c_) = *(const int4*)((SRC) + r_ * (STRIDE) + c_); \
        *(int4*)((DST) + (r_ + 32) * LDP + c_) =                                      \
            *(const int4*)((SRC) + (r_ + 32) * (STRIDE) + c_);                        \
    }

// full 64x64 mma loading both A and B from shared (proj kernel)
__device__ __forceinline__ void mma_tile_64(const __half* Qs, const __half* Ks,
                                            float acc[16], int lane, int wy, int wx) {
    uint32_t a_addr = sptr(Qs + (wy * 16 + (lane & 15)) * LDP + ((lane >> 4) << 3));
    int brow = wx * 32 + (lane & 7) + ((lane >> 4) << 3);
    int bcol = ((lane >> 3) & 1) << 3;
    uint32_t b_addr0 = sptr(Ks + brow * LDP + bcol);
    uint32_t b_addr1 = b_addr0 + 16 * LDP * 2;
#pragma unroll
    for (int kc = 0; kc < 4; kc++) {
        uint32_t a0, a1, a2, a3, b0, b1, b2, b3, b4, b5, b6, b7;
        ldsm4(a0, a1, a2, a3, a_addr + kc * 32);
        ldsm4(b0, b1, b2, b3, b_addr0 + kc * 32);
        ldsm4(b4, b5, b6, b7, b_addr1 + kc * 32);
        mma16816(acc + 0,  a0, a1, a2, a3, b0, b1);
        mma16816(acc + 4,  a0, a1, a2, a3, b2, b3);
        mma16816(acc + 8,  a0, a1, a2, a3, b4, b5);
        mma16816(acc + 12, a0, a1, a2, a3, b6, b7);
    }
}

// ---------------- kernel 1: prep ----------------
__global__ void prep_kernel(const float* __restrict__ x, const float* __restrict__ pe,
                            const float* __restrict__ Wq, const float* __restrict__ Wk) {
    int idx = blockIdx.x * 256 + threadIdx.x;
    if (idx < 8192 * 256) {
        int row = idx >> 8;
        int l = row & (LSEQ - 1);
        int c = idx & 255;
        g_qkin[idx] = __float2half(x[idx] + pe[l * 256 + c]);
        return;
    }
    int i2 = idx - 8192 * 256;
    if (i2 < 1024 * 256) {
        int n = i2 >> 8, kk = i2 & 255;
        float w = (n < 512) ? Wq[kk * 512 + n] : Wk[kk * 512 + (n - 512)];
        g_Wt[i2] = __float2half(w);
        return;
    }
    int i3 = i2 - 1024 * 256;
    if (i3 < NBH * DBINS) g_S[i3] = 0.f;
}

// ---------------- kernel 2: Q/K projection GEMM ----------------
__global__ void __launch_bounds__(256) proj_kernel(const float* __restrict__ bq,
                                                   const float* __restrict__ bk) {
    __shared__ __half As[64 * LDP];
    __shared__ __half Bs[64 * LDP];
    int tid = threadIdx.x, lane = tid & 31, w = tid >> 5, wy = w >> 1, wx = w & 1;
    int m0 = blockIdx.x << 6, n0 = blockIdx.y << 6;
    float acc[16];
#pragma unroll
    for (int i = 0; i < 16; i++) acc[i] = 0.f;
    for (int ks = 0; ks < 4; ks++) {
        __syncthreads();
        LOAD_TILE(As, g_qkin + m0 * 256 + (ks << 6), 256);
        LOAD_TILE(Bs, g_Wt + n0 * 256 + (ks << 6), 256);
        __syncthreads();
        mma_tile_64(As, Bs, acc, lane, wy, wx);
    }
    int g = lane >> 2, tc = lane & 3;
#pragma unroll
    for (int nt = 0; nt < 4; nt++) {
#pragma unroll
        for (int hh = 0; hh < 2; hh++) {
            int row = m0 + wy * 16 + g + (hh << 3);
            int col = n0 + wx * 32 + nt * 8 + tc * 2;
            float v0 = acc[nt * 4 + hh * 2 + 0];
            float v1 = acc[nt * 4 + hh * 2 + 1];
            int b = row >> 11, l = row & (LSEQ - 1);
            if (col < 512) {
                // fold d^-0.5 and log2(e) into Q so score-exp is a single ex2
                v0 = (v0 + bq[col]) * (0.125f * LOG2E);
                v1 = (v1 + bq[col + 1]) * (0.125f * LOG2E);
                int hd = col >> 6, dd = col & 63;
                *(__half2*)(g_Q + ((b * NH + hd) * LSEQ + l) * DDIM + dd) =
                    __floats2half2_rn(v0, v1);
            } else {
                int cj = col - 512;
                v0 += bk[cj];
                v1 += bk[cj + 1];
                int hd = cj >> 6, dd = cj & 63;
                *(__half2*)(g_K + ((b * NH + hd) * LSEQ + l) * DDIM + dd) =
                    __floats2half2_rn(v0, v1);
            }
        }
    }
}

// ---------------- kernel 3: V (sigmoid(x @ Wv), flipped) ----------------
__global__ void __launch_bounds__(256) v_kernel(const float* __restrict__ x,
                                                const float* __restrict__ Wv) {
    __shared__ float Wsh[256 * 8];
    __shared__ float Xsh[32 * 257];
    int tid = threadIdx.x;
    for (int i = tid; i < 2048; i += 256) Wsh[i] = Wv[i];
    int row0 = blockIdx.x * 32;
    for (int i = tid; i < 8192; i += 256) {
        int r = i >> 8, c = i & 255;
        Xsh[r * 257 + c] = x[(row0 + r) * 256 + c];
    }
    __syncthreads();
    int r = tid >> 3, h = tid & 7;
    int bl = row0 + r;
    float s = 0.f;
#pragma unroll 8
    for (int kk = 0; kk < 256; kk++) s += Xsh[r * 257 + kk] * Wsh[kk * 8 + h];
    float v = 1.f / (1.f + __expf(-s));
    int b = bl >> 11, l = bl & (LSEQ - 1);
    g_V[(b * NH + h) * LSEQ + (LSEQ - 1 - l)] = v;
}

// ---------------- kernel 4: attention (pipelined) ----------------
__global__ void __launch_bounds__(256) attn_kernel() {
    __shared__ __half Qs[64 * LDP];
    __shared__ __half Kb[3][64 * LDP];
    __shared__ float dsh[64];
    __shared__ float Ssh[DBINS];
    __shared__ float Vsh[5 * 64];

    int tid = threadIdx.x, lane = tid & 31, w = tid >> 5, wy = w >> 1, wx = w & 1;
    int qt = blockIdx.x, bh = blockIdx.y;
    int q0 = qt << 6;
    const __half* Qg = g_Q + (bh * LSEQ + q0) * DDIM;
    const __half* Kg = g_K + bh * LSEQ * DDIM;

    // async-load Q tile + first two K tiles
    cp_tile(Qs, Qg, tid);
    cp_tile(Kb[0], Kg, tid);
    cp_commit();                    // group 0: Qs + K0
    cp_tile(Kb[1], Kg + 64 * DDIM, tid);
    cp_commit();                    // group 1: K1

    if (tid < 64) dsh[tid] = 0.f;
    if (tid < DBINS) Ssh[tid] = 0.f;
    if (tid == 255) Ssh[256] = 0.f;

    cp_wait1();                     // Qs + K0 landed
    __syncthreads();

    // hoist Q fragments (loop-invariant)
    uint32_t Af[4][4];
    {
        uint32_t a_addr = sptr(Qs + (wy * 16 + (lane & 15)) * LDP + ((lane >> 4) << 3));
#pragma unroll
        for (int kc = 0; kc < 4; kc++)
            ldsm4(Af[kc][0], Af[kc][1], Af[kc][2], Af[kc][3], a_addr + kc * 32);
    }

    int g = lane >> 2, tc = lane & 3;
    float dsum0 = 0.f, dsum1 = 0.f;

    // ---- Phase 1: softmax denominators over all 32 K tiles ----
    for (int kt = 0; kt < 32; kt++) {
        if (kt > 0) { cp_wait1(); __syncthreads(); }
        if (kt + 2 < 32) cp_tile(Kb[(kt + 2) % 3], Kg + (kt + 2) * 64 * DDIM, tid);
        cp_commit();                // one group per iteration -> constant wait_group 1
        float acc[16];
#pragma unroll
        for (int i = 0; i < 16; i++) acc[i] = 0.f;
        mma_b(Kb[kt % 3], Af, acc, lane, wx);
#pragma unroll
        for (int nt = 0; nt < 4; nt++) {
            dsum0 += ex2f(acc[nt * 4 + 0]) + ex2f(acc[nt * 4 + 1]);
            dsum1 += ex2f(acc[nt * 4 + 2]) + ex2f(acc[nt * 4 + 3]);
        }
    }
    // reduce over the 4 tc-lanes sharing a row before hitting shared atomics
    dsum0 += __shfl_xor_sync(0xffffffffu, dsum0, 1);
    dsum0 += __shfl_xor_sync(0xffffffffu, dsum0, 2);
    dsum1 += __shfl_xor_sync(0xffffffffu, dsum1, 1);
    dsum1 += __shfl_xor_sync(0xffffffffu, dsum1, 2);
    if (tc == 0) {
        atomicAdd(&dsh[wy * 16 + g], dsum0);
        atomicAdd(&dsh[wy * 16 + g + 8], dsum1);
    }
    __syncthreads();

    int kt_lo = qt >= 2 ? qt - 2 : 0;
    int kt_hi = qt <= 29 ? qt + 2 : 31;
    int nb = kt_hi - kt_lo + 1;

    if (tid < 64) dsh[tid] = 1.f / dsh[tid];
    const float* Vg = g_V + bh * LSEQ;
    for (int i = tid; i < nb * 64; i += 256) Vsh[i] = Vg[kt_lo * 64 + i];
    __syncthreads();   // buffers free + dsh inverted

    // ---- Phase 2: band tiles, bin by diagonal j = 128 + k - q ----
    cp_tile(Kb[0], Kg + kt_lo * 64 * DDIM, tid);
    cp_commit();
    if (nb > 1) cp_tile(Kb[1], Kg + (kt_lo + 1) * 64 * DDIM, tid);
    cp_commit();

    for (int i = 0; i < nb; i++) {
        int kt = kt_lo + i;
        cp_wait1();
        __syncthreads();
        if (i + 2 < nb) cp_tile(Kb[(i + 2) % 3], Kg + (kt + 2) * 64 * DDIM, tid);
        cp_commit();
        float acc[16];
#pragma unroll
        for (int ii = 0; ii < 16; ii++) acc[ii] = 0.f;
        mma_b(Kb[i % 3], Af, acc, lane, wx);
#pragma unroll
        for (int nt = 0; nt < 4; nt++) {
            int kb = (kt << 6) + wx * 32 + nt * 8 + tc * 2;
#pragma unroll
            for (int hh = 0; hh < 2; hh++) {
                int q = q0 + wy * 16 + g + (hh << 3);
                float inv = dsh[wy * 16 + g + (hh << 3)];
#pragma unroll
                for (int cc = 0; cc < 2; cc++) {
                    int k = kb + cc;
                    int j = MDIST + k - q;
                    if (j >= 0 && j < DBINS) {
                        float e = ex2f(acc[nt * 4 + hh * 2 + cc]);
                        atomicAdd(&Ssh[j], e * inv * Vsh[k - (kt_lo << 6)]);
                    }
                }
            }
        }
    }
    __syncthreads();
    if (tid < DBINS) atomicAdd(&g_S[bh * DBINS + tid], Ssh[tid]);
    if (tid == 255) atomicAdd(&g_S[bh * DBINS + 256], Ssh[256]);
}

// ---------------- kernel 5: window smoothing + output ----------------
__global__ void final_kernel(float* __restrict__ out) {
    int idx = blockIdx.x * 256 + threadIdx.x;
    if (idx >= NB * DBINS * NH) return;
    int h = idx & 7;
    int j = (idx >> 3) % DBINS;
    int b = idx / (DBINS * NH);
    const float* S = g_S + (b * NH + h) * DBINS;
    float s = S[j];
    float cnt = 1.f;
    if (j > 0)         { s += S[j - 1]; cnt += 1.f; }
    if (j < DBINS - 1) { s += S[j + 1]; cnt += 1.f; }
    out[idx] = s / cnt;
}

// ---------------- launch ----------------
extern "C" void kernel_launch(void* const* d_in, const int* in_sizes, int n_in,
                              void* d_out, int out_size) {
    const float* x  = (const float*)d_in[0];
    const float* pe = (const float*)d_in[1];
    const float* Wq = (const float*)d_in[2];
    const float* bq = (const float*)d_in[3];
    const float* Wk = (const float*)d_in[4];
    const float* bk = (const float*)d_in[5];
    const float* Wv = (const float*)d_in[6];
    float* out = (float*)d_out;

    int prep_total = 8192 * 256 + 1024 * 256 + NBH * DBINS;
    prep_kernel<<<(prep_total + 255) / 256, 256>>>(x, pe, Wq, Wk);
    proj_kernel<<<dim3(128, 16), 256>>>(bq, bk);
    v_kernel<<<256, 256>>>(x, Wv);
    attn_kernel<<<dim3(32, 32), 256>>>();
    final_kernel<<<(NB * DBINS * NH + 255) / 256, 256>>>(out);
}